// round 11
// baseline (speedup 1.0000x reference)
#include <cuda_runtime.h>

// LiveniumJoint closed form: h stays in span{h0, a0n, a1n, a2n}.
// R11 = R9 exactly (reg anchors + in-kernel per-warp prep, j-outer 24-LDG
// burst, L2 prefetch of next batch issued WITH the burst, lane-parked single
// chain, output from h regs, plain STG) + persistent grid (296 blocks =
// 2/SM x 148: zero wave transitions, prefetch warm for ~14 iterations).

#define DD 768
#define VV 192            // float4 per row
#define KPL 6             // float4 per lane (192/32)
#define RB 4              // rows per warp-batch
#define FULLMASK 0xffffffffu

__device__ __forceinline__ float rcpa(float x) {
    float y; asm("rcp.approx.ftz.f32 %0,%1;" : "=f"(y) : "f"(x)); return y;
}
__device__ __forceinline__ float rsqa(float x) {
    float y; asm("rsqrt.approx.ftz.f32 %0,%1;" : "=f"(y) : "f"(x)); return y;
}
__device__ __forceinline__ float ex2a(float x) {
    float y; asm("ex2.approx.ftz.f32 %0,%1;" : "=f"(y) : "f"(x)); return y;
}
__device__ __forceinline__ void pfL2(const void* p) {
    asm volatile("prefetch.global.L2 [%0];" :: "l"(p));
}

__global__ void liv_fused(const float* __restrict__ h0,
                          const float* __restrict__ anchors,
                          float* __restrict__ out_h,
                          float* __restrict__ out_al,
                          int B) {
    const int tid = threadIdx.x, lane = tid & 31;

    // ---- per-warp anchor prep, all in registers (anchors L2-hot) ----
    float4 A0[KPL], A1[KPL], A2[KPL];
    {
        const float4* av = (const float4*)anchors;
        #pragma unroll
        for (int k = 0; k < KPL; k++) {
            A0[k] = __ldg(av + k * 32 + lane);
            A1[k] = __ldg(av + VV + k * 32 + lane);
            A2[k] = __ldg(av + 2 * VV + k * 32 + lane);
        }
    }
    float n0 = 0.f, n1 = 0.f, n2 = 0.f, d01 = 0.f, d02 = 0.f, d12 = 0.f;
    #pragma unroll
    for (int k = 0; k < KPL; k++) {
        n0 = fmaf(A0[k].x, A0[k].x, n0); n0 = fmaf(A0[k].y, A0[k].y, n0);
        n0 = fmaf(A0[k].z, A0[k].z, n0); n0 = fmaf(A0[k].w, A0[k].w, n0);
        n1 = fmaf(A1[k].x, A1[k].x, n1); n1 = fmaf(A1[k].y, A1[k].y, n1);
        n1 = fmaf(A1[k].z, A1[k].z, n1); n1 = fmaf(A1[k].w, A1[k].w, n1);
        n2 = fmaf(A2[k].x, A2[k].x, n2); n2 = fmaf(A2[k].y, A2[k].y, n2);
        n2 = fmaf(A2[k].z, A2[k].z, n2); n2 = fmaf(A2[k].w, A2[k].w, n2);
        d01 = fmaf(A0[k].x, A1[k].x, d01); d01 = fmaf(A0[k].y, A1[k].y, d01);
        d01 = fmaf(A0[k].z, A1[k].z, d01); d01 = fmaf(A0[k].w, A1[k].w, d01);
        d02 = fmaf(A0[k].x, A2[k].x, d02); d02 = fmaf(A0[k].y, A2[k].y, d02);
        d02 = fmaf(A0[k].z, A2[k].z, d02); d02 = fmaf(A0[k].w, A2[k].w, d02);
        d12 = fmaf(A1[k].x, A2[k].x, d12); d12 = fmaf(A1[k].y, A2[k].y, d12);
        d12 = fmaf(A1[k].z, A2[k].z, d12); d12 = fmaf(A1[k].w, A2[k].w, d12);
    }
    #pragma unroll
    for (int o = 16; o; o >>= 1) {
        n0  += __shfl_xor_sync(FULLMASK, n0,  o);
        n1  += __shfl_xor_sync(FULLMASK, n1,  o);
        n2  += __shfl_xor_sync(FULLMASK, n2,  o);
        d01 += __shfl_xor_sync(FULLMASK, d01, o);
        d02 += __shfl_xor_sync(FULLMASK, d02, o);
        d12 += __shfl_xor_sync(FULLMASK, d12, o);
    }
    const float i0 = 1.f / fmaxf(sqrtf(n0), 1e-12f);
    const float i1 = 1.f / fmaxf(sqrtf(n1), 1e-12f);
    const float i2 = 1.f / fmaxf(sqrtf(n2), 1e-12f);
    #pragma unroll
    for (int k = 0; k < KPL; k++) {
        A0[k].x *= i0; A0[k].y *= i0; A0[k].z *= i0; A0[k].w *= i0;
        A1[k].x *= i1; A1[k].y *= i1; A1[k].z *= i1; A1[k].w *= i1;
        A2[k].x *= i2; A2[k].y *= i2; A2[k].z *= i2; A2[k].w *= i2;
    }
    const float G00 = n0 * i0 * i0, G11 = n1 * i1 * i1, G22 = n2 * i2 * i2;
    const float G01 = d01 * i0 * i1, G02 = d02 * i0 * i2, G12 = d12 * i1 * i2;

    const int gw = (blockIdx.x * blockDim.x + tid) >> 5;
    const int nwarps = (gridDim.x * blockDim.x) >> 5;
    const int nbatch = (B + RB - 1) / RB;
    const float4* hp = (const float4*)h0;

    for (int b = gw; b < nbatch; b += nwarps) {
        const int base = b * RB;

        // ---- burst: 24 LDG.128 in flight ----
        float4 h[RB][KPL];
        #pragma unroll
        for (int j = 0; j < RB; j++) {
            int row = base + j; if (row >= B) row = B - 1;
            const float4* rp = hp + (size_t)row * VV;
            #pragma unroll
            for (int k = 0; k < KPL; k++) h[j][k] = __ldg(rp + k * 32 + lane);
        }

        // ---- L2-prefetch next batch (96 lines, 3 warp instructions),
        //      issued WITH the burst for maximum lead time (R9 placement) ----
        {
            const int nb = b + nwarps;
            if (nb < nbatch) {
                const size_t nbase = (size_t)nb * RB;
                #pragma unroll
                for (int t = 0; t < 3; t++) {
                    int f = t * 32 + lane;            // 0..95
                    int r = f / 24, lc = f - r * 24;  // row, 128B line
                    const char* a = (const char*)(hp + (nbase + r) * VV) + lc * 128;
                    pfL2(a);
                }
            }
        }

        // ---- per-row dots + reduce; park scalars in lane j ----
        float myN = 0.f, myT0 = 0.f, myT1 = 0.f, myT2 = 0.f;
        #pragma unroll
        for (int j = 0; j < RB; j++) {
            float N0 = 0.f, T0 = 0.f, T1 = 0.f, T2 = 0.f;
            #pragma unroll
            for (int k = 0; k < KPL; k++) {
                const float4 v = h[j][k];
                N0 = fmaf(v.x, v.x, N0);
                N0 = fmaf(v.y, v.y, N0);
                N0 = fmaf(v.z, v.z, N0);
                N0 = fmaf(v.w, v.w, N0);
                T0 = fmaf(v.x, A0[k].x, T0);
                T0 = fmaf(v.y, A0[k].y, T0);
                T0 = fmaf(v.z, A0[k].z, T0);
                T0 = fmaf(v.w, A0[k].w, T0);
                T1 = fmaf(v.x, A1[k].x, T1);
                T1 = fmaf(v.y, A1[k].y, T1);
                T1 = fmaf(v.z, A1[k].z, T1);
                T1 = fmaf(v.w, A1[k].w, T1);
                T2 = fmaf(v.x, A2[k].x, T2);
                T2 = fmaf(v.y, A2[k].y, T2);
                T2 = fmaf(v.z, A2[k].z, T2);
                T2 = fmaf(v.w, A2[k].w, T2);
            }
            #pragma unroll
            for (int o = 16; o; o >>= 1) {
                N0 += __shfl_xor_sync(FULLMASK, N0, o);
                T0 += __shfl_xor_sync(FULLMASK, T0, o);
                T1 += __shfl_xor_sync(FULLMASK, T1, o);
                T2 += __shfl_xor_sync(FULLMASK, T2, o);
            }
            if (lane == j) { myN = N0; myT0 = T0; myT1 = T1; myT2 = T2; }
        }

        // ---- ONE branchless chain: lane j computes row base+j ----
        float p = 1.f, q0 = 0.f, q1 = 0.f, q2 = 0.f;
        float al0 = 0.f, al1 = 0.f, al2 = 0.f;
        const float KK = 28.853900817779268f;  // 20 * log2(e)
        #pragma unroll
        for (int s = 0; s < 7; s++) {
            float s0 = fmaf(p, myT0, fmaf(q0, G00, fmaf(q1, G01, q2 * G02)));
            float s1 = fmaf(p, myT1, fmaf(q0, G01, fmaf(q1, G11, q2 * G12)));
            float s2 = fmaf(p, myT2, fmaf(q0, G02, fmaf(q1, G12, q2 * G22)));
            float qT = fmaf(q0, myT0, fmaf(q1, myT1, q2 * myT2));
            float n2r = fmaf(p, fmaf(p, myN, qT),
                             fmaf(q0, s0, fmaf(q1, s1, q2 * s2)));
            float inv = rsqa(fmaxf(n2r, 1e-24f));
            al0 = s0 * inv; al1 = s1 * inv; al2 = s2 * inv;
            if (s == 6) break;

            float e0 = ex2a(KK * al0);
            float e1 = ex2a(KK * al1);
            float e2 = ex2a(KK * al2);
            float invW = rcpa(e0 + e1 + e2);
            float w0 = e0 * invW, w1 = e1 * invW, w2 = e2 * invW;

            float c = fmaf(w0, al0, fmaf(w1, al1, w2 * al2));
            float beta = fmaf(-0.05f, c, 1.f);
            float n = n2r * inv;            // sqrt(n2)
            float delta = 0.05f * n;
            p *= beta;
            q0 = fmaf(beta, q0, delta * w0);
            q1 = fmaf(beta, q1, delta * w1);
            q2 = fmaf(beta, q2, delta * w2);

            float t2 = fmaf(w0 * w0, G00,
                       fmaf(w1 * w1, G11,
                       fmaf(w2 * w2, G22,
                       2.f * fmaf(w0 * w1, G01,
                             fmaf(w0 * w2, G02, w1 * w2 * G12)))));
            float n2b = n2r * fmaf(0.0025f, t2 - c * c, 1.f);
            float g = fminf(1.f, 10.f * rsqa(n2b));
            p *= g; q0 *= g; q1 *= g; q2 *= g;
        }

        // ---- outputs: broadcast (p,q) from lane j, h from regs ----
        #pragma unroll
        for (int j = 0; j < RB; j++) {
            const int row = base + j;
            const float pj  = __shfl_sync(FULLMASK, p,  j);
            const float q0j = __shfl_sync(FULLMASK, q0, j);
            const float q1j = __shfl_sync(FULLMASK, q1, j);
            const float q2j = __shfl_sync(FULLMASK, q2, j);
            if (row < B) {
                float4* op = (float4*)out_h + (size_t)row * VV;
                #pragma unroll
                for (int k = 0; k < KPL; k++) {
                    float4 o;
                    o.x = fmaf(pj, h[j][k].x, fmaf(q0j, A0[k].x, fmaf(q1j, A1[k].x, q2j * A2[k].x)));
                    o.y = fmaf(pj, h[j][k].y, fmaf(q0j, A0[k].y, fmaf(q1j, A1[k].y, q2j * A2[k].y)));
                    o.z = fmaf(pj, h[j][k].z, fmaf(q0j, A0[k].z, fmaf(q1j, A1[k].z, q2j * A2[k].z)));
                    o.w = fmaf(pj, h[j][k].w, fmaf(q0j, A0[k].w, fmaf(q1j, A1[k].w, q2j * A2[k].w)));
                    op[k * 32 + lane] = o;
                }
            }
        }
        if (lane < RB && base + lane < B) {
            float* ap = out_al + (size_t)(base + lane) * 3;
            ap[0] = al0; ap[1] = al1; ap[2] = al2;
        }
    }
}

// ---------------------------------------------------------------------------
extern "C" void kernel_launch(void* const* d_in, const int* in_sizes, int n_in,
                              void* d_out, int out_size) {
    const float* h0 = (const float*)d_in[0];       // [B, 768]
    const float* anchors = (const float*)d_in[1];  // [3, 768]
    const int B = in_sizes[0] / DD;

    float* out_h = (float*)d_out;                    // [B, 768]
    float* out_al = (float*)d_out + (size_t)B * DD;  // [B, 3]

    const int threads = 128;              // 4 warps/block
    int nbatch = (B + RB - 1) / RB;       // 16384 batches of 4 rows
    // Persistent grid: 2 blocks/SM x 148 SMs; single wave, warm prefetch.
    int blocks = 296;
    int total_warps = blocks * (threads / 32);
    if (total_warps > nbatch) blocks = (nbatch + 3) / 4;
    liv_fused<<<blocks, threads>>>(h0, anchors, out_h, out_al, B);
}

// round 13
// speedup vs baseline: 1.0764x; 1.0764x over previous
#include <cuda_runtime.h>

// LiveniumJoint closed form: h stays in span{h0, a0n, a1n, a2n}.
// R13 = R12 resubmitted (infra failure last round, never ran).
// R9 body exactly (reg anchors + in-kernel per-warp prep, j-outer 24-LDG
// burst, L2 prefetch of next batch issued with the burst, lane-parked single
// chain, output from h regs, plain STG), grid = 2048 blocks x 2 batches/warp
// (perfect balance + dense CTA-swap overlap of bursts with tails).

#define DD 768
#define VV 192            // float4 per row
#define KPL 6             // float4 per lane (192/32)
#define RB 4              // rows per warp-batch
#define FULLMASK 0xffffffffu

__device__ __forceinline__ float rcpa(float x) {
    float y; asm("rcp.approx.ftz.f32 %0,%1;" : "=f"(y) : "f"(x)); return y;
}
__device__ __forceinline__ float rsqa(float x) {
    float y; asm("rsqrt.approx.ftz.f32 %0,%1;" : "=f"(y) : "f"(x)); return y;
}
__device__ __forceinline__ float ex2a(float x) {
    float y; asm("ex2.approx.ftz.f32 %0,%1;" : "=f"(y) : "f"(x)); return y;
}
__device__ __forceinline__ void pfL2(const void* p) {
    asm volatile("prefetch.global.L2 [%0];" :: "l"(p));
}

__global__ void liv_fused(const float* __restrict__ h0,
                          const float* __restrict__ anchors,
                          float* __restrict__ out_h,
                          float* __restrict__ out_al,
                          int B) {
    const int tid = threadIdx.x, lane = tid & 31;

    // ---- per-warp anchor prep, all in registers (anchors L2-hot) ----
    float4 A0[KPL], A1[KPL], A2[KPL];
    {
        const float4* av = (const float4*)anchors;
        #pragma unroll
        for (int k = 0; k < KPL; k++) {
            A0[k] = __ldg(av + k * 32 + lane);
            A1[k] = __ldg(av + VV + k * 32 + lane);
            A2[k] = __ldg(av + 2 * VV + k * 32 + lane);
        }
    }
    float n0 = 0.f, n1 = 0.f, n2 = 0.f, d01 = 0.f, d02 = 0.f, d12 = 0.f;
    #pragma unroll
    for (int k = 0; k < KPL; k++) {
        n0 = fmaf(A0[k].x, A0[k].x, n0); n0 = fmaf(A0[k].y, A0[k].y, n0);
        n0 = fmaf(A0[k].z, A0[k].z, n0); n0 = fmaf(A0[k].w, A0[k].w, n0);
        n1 = fmaf(A1[k].x, A1[k].x, n1); n1 = fmaf(A1[k].y, A1[k].y, n1);
        n1 = fmaf(A1[k].z, A1[k].z, n1); n1 = fmaf(A1[k].w, A1[k].w, n1);
        n2 = fmaf(A2[k].x, A2[k].x, n2); n2 = fmaf(A2[k].y, A2[k].y, n2);
        n2 = fmaf(A2[k].z, A2[k].z, n2); n2 = fmaf(A2[k].w, A2[k].w, n2);
        d01 = fmaf(A0[k].x, A1[k].x, d01); d01 = fmaf(A0[k].y, A1[k].y, d01);
        d01 = fmaf(A0[k].z, A1[k].z, d01); d01 = fmaf(A0[k].w, A1[k].w, d01);
        d02 = fmaf(A0[k].x, A2[k].x, d02); d02 = fmaf(A0[k].y, A2[k].y, d02);
        d02 = fmaf(A0[k].z, A2[k].z, d02); d02 = fmaf(A0[k].w, A2[k].w, d02);
        d12 = fmaf(A1[k].x, A2[k].x, d12); d12 = fmaf(A1[k].y, A2[k].y, d12);
        d12 = fmaf(A1[k].z, A2[k].z, d12); d12 = fmaf(A1[k].w, A2[k].w, d12);
    }
    #pragma unroll
    for (int o = 16; o; o >>= 1) {
        n0  += __shfl_xor_sync(FULLMASK, n0,  o);
        n1  += __shfl_xor_sync(FULLMASK, n1,  o);
        n2  += __shfl_xor_sync(FULLMASK, n2,  o);
        d01 += __shfl_xor_sync(FULLMASK, d01, o);
        d02 += __shfl_xor_sync(FULLMASK, d02, o);
        d12 += __shfl_xor_sync(FULLMASK, d12, o);
    }
    const float i0 = 1.f / fmaxf(sqrtf(n0), 1e-12f);
    const float i1 = 1.f / fmaxf(sqrtf(n1), 1e-12f);
    const float i2 = 1.f / fmaxf(sqrtf(n2), 1e-12f);
    #pragma unroll
    for (int k = 0; k < KPL; k++) {
        A0[k].x *= i0; A0[k].y *= i0; A0[k].z *= i0; A0[k].w *= i0;
        A1[k].x *= i1; A1[k].y *= i1; A1[k].z *= i1; A1[k].w *= i1;
        A2[k].x *= i2; A2[k].y *= i2; A2[k].z *= i2; A2[k].w *= i2;
    }
    const float G00 = n0 * i0 * i0, G11 = n1 * i1 * i1, G22 = n2 * i2 * i2;
    const float G01 = d01 * i0 * i1, G02 = d02 * i0 * i2, G12 = d12 * i1 * i2;

    const int gw = (blockIdx.x * blockDim.x + tid) >> 5;
    const int nwarps = (gridDim.x * blockDim.x) >> 5;
    const int nbatch = (B + RB - 1) / RB;
    const float4* hp = (const float4*)h0;

    for (int b = gw; b < nbatch; b += nwarps) {
        const int base = b * RB;

        // ---- burst: 24 LDG.128 in flight ----
        float4 h[RB][KPL];
        #pragma unroll
        for (int j = 0; j < RB; j++) {
            int row = base + j; if (row >= B) row = B - 1;
            const float4* rp = hp + (size_t)row * VV;
            #pragma unroll
            for (int k = 0; k < KPL; k++) h[j][k] = __ldg(rp + k * 32 + lane);
        }

        // ---- L2-prefetch next batch (96 lines, 3 warp instructions) ----
        {
            const int nb = b + nwarps;
            if (nb < nbatch) {
                const size_t nbase = (size_t)nb * RB;
                #pragma unroll
                for (int t = 0; t < 3; t++) {
                    int f = t * 32 + lane;            // 0..95
                    int r = f / 24, lc = f - r * 24;  // row, 128B line
                    const char* a = (const char*)(hp + (nbase + r) * VV) + lc * 128;
                    pfL2(a);
                }
            }
        }

        // ---- per-row dots + reduce; park scalars in lane j ----
        float myN = 0.f, myT0 = 0.f, myT1 = 0.f, myT2 = 0.f;
        #pragma unroll
        for (int j = 0; j < RB; j++) {
            float N0 = 0.f, T0 = 0.f, T1 = 0.f, T2 = 0.f;
            #pragma unroll
            for (int k = 0; k < KPL; k++) {
                const float4 v = h[j][k];
                N0 = fmaf(v.x, v.x, N0);
                N0 = fmaf(v.y, v.y, N0);
                N0 = fmaf(v.z, v.z, N0);
                N0 = fmaf(v.w, v.w, N0);
                T0 = fmaf(v.x, A0[k].x, T0);
                T0 = fmaf(v.y, A0[k].y, T0);
                T0 = fmaf(v.z, A0[k].z, T0);
                T0 = fmaf(v.w, A0[k].w, T0);
                T1 = fmaf(v.x, A1[k].x, T1);
                T1 = fmaf(v.y, A1[k].y, T1);
                T1 = fmaf(v.z, A1[k].z, T1);
                T1 = fmaf(v.w, A1[k].w, T1);
                T2 = fmaf(v.x, A2[k].x, T2);
                T2 = fmaf(v.y, A2[k].y, T2);
                T2 = fmaf(v.z, A2[k].z, T2);
                T2 = fmaf(v.w, A2[k].w, T2);
            }
            #pragma unroll
            for (int o = 16; o; o >>= 1) {
                N0 += __shfl_xor_sync(FULLMASK, N0, o);
                T0 += __shfl_xor_sync(FULLMASK, T0, o);
                T1 += __shfl_xor_sync(FULLMASK, T1, o);
                T2 += __shfl_xor_sync(FULLMASK, T2, o);
            }
            if (lane == j) { myN = N0; myT0 = T0; myT1 = T1; myT2 = T2; }
        }

        // ---- ONE branchless chain: lane j computes row base+j ----
        float p = 1.f, q0 = 0.f, q1 = 0.f, q2 = 0.f;
        float al0 = 0.f, al1 = 0.f, al2 = 0.f;
        const float KK = 28.853900817779268f;  // 20 * log2(e)
        #pragma unroll
        for (int s = 0; s < 7; s++) {
            float s0 = fmaf(p, myT0, fmaf(q0, G00, fmaf(q1, G01, q2 * G02)));
            float s1 = fmaf(p, myT1, fmaf(q0, G01, fmaf(q1, G11, q2 * G12)));
            float s2 = fmaf(p, myT2, fmaf(q0, G02, fmaf(q1, G12, q2 * G22)));
            float qT = fmaf(q0, myT0, fmaf(q1, myT1, q2 * myT2));
            float n2r = fmaf(p, fmaf(p, myN, qT),
                             fmaf(q0, s0, fmaf(q1, s1, q2 * s2)));
            float inv = rsqa(fmaxf(n2r, 1e-24f));
            al0 = s0 * inv; al1 = s1 * inv; al2 = s2 * inv;
            if (s == 6) break;

            float e0 = ex2a(KK * al0);
            float e1 = ex2a(KK * al1);
            float e2 = ex2a(KK * al2);
            float invW = rcpa(e0 + e1 + e2);
            float w0 = e0 * invW, w1 = e1 * invW, w2 = e2 * invW;

            float c = fmaf(w0, al0, fmaf(w1, al1, w2 * al2));
            float beta = fmaf(-0.05f, c, 1.f);
            float n = n2r * inv;            // sqrt(n2)
            float delta = 0.05f * n;
            p *= beta;
            q0 = fmaf(beta, q0, delta * w0);
            q1 = fmaf(beta, q1, delta * w1);
            q2 = fmaf(beta, q2, delta * w2);

            float t2 = fmaf(w0 * w0, G00,
                       fmaf(w1 * w1, G11,
                       fmaf(w2 * w2, G22,
                       2.f * fmaf(w0 * w1, G01,
                             fmaf(w0 * w2, G02, w1 * w2 * G12)))));
            float n2b = n2r * fmaf(0.0025f, t2 - c * c, 1.f);
            float g = fminf(1.f, 10.f * rsqa(n2b));
            p *= g; q0 *= g; q1 *= g; q2 *= g;
        }

        // ---- outputs: broadcast (p,q) from lane j, h from regs ----
        #pragma unroll
        for (int j = 0; j < RB; j++) {
            const int row = base + j;
            const float pj  = __shfl_sync(FULLMASK, p,  j);
            const float q0j = __shfl_sync(FULLMASK, q0, j);
            const float q1j = __shfl_sync(FULLMASK, q1, j);
            const float q2j = __shfl_sync(FULLMASK, q2, j);
            if (row < B) {
                float4* op = (float4*)out_h + (size_t)row * VV;
                #pragma unroll
                for (int k = 0; k < KPL; k++) {
                    float4 o;
                    o.x = fmaf(pj, h[j][k].x, fmaf(q0j, A0[k].x, fmaf(q1j, A1[k].x, q2j * A2[k].x)));
                    o.y = fmaf(pj, h[j][k].y, fmaf(q0j, A0[k].y, fmaf(q1j, A1[k].y, q2j * A2[k].y)));
                    o.z = fmaf(pj, h[j][k].z, fmaf(q0j, A0[k].z, fmaf(q1j, A1[k].z, q2j * A2[k].z)));
                    o.w = fmaf(pj, h[j][k].w, fmaf(q0j, A0[k].w, fmaf(q1j, A1[k].w, q2j * A2[k].w)));
                    op[k * 32 + lane] = o;
                }
            }
        }
        if (lane < RB && base + lane < B) {
            float* ap = out_al + (size_t)(base + lane) * 3;
            ap[0] = al0; ap[1] = al1; ap[2] = al2;
        }
    }
}

// ---------------------------------------------------------------------------
extern "C" void kernel_launch(void* const* d_in, const int* in_sizes, int n_in,
                              void* d_out, int out_size) {
    const float* h0 = (const float*)d_in[0];       // [B, 768]
    const float* anchors = (const float*)d_in[1];  // [3, 768]
    const int B = in_sizes[0] / DD;

    float* out_h = (float*)d_out;                    // [B, 768]
    float* out_al = (float*)d_out + (size_t)B * DD;  // [B, 3]

    const int threads = 128;              // 4 warps/block
    int nbatch = (B + RB - 1) / RB;       // 16384 batches of 4 rows
    // 2048 blocks -> 8192 warps -> exactly 2 batches/warp: perfect balance,
    // dense CTA-swap so fresh bursts overlap other CTAs' chain/store tails.
    int blocks = 2048;
    int total_warps = blocks * (threads / 32);
    if (total_warps > nbatch) blocks = (nbatch + 3) / 4;
    liv_fused<<<blocks, threads>>>(h0, anchors, out_h, out_al, B);
}

// round 15
// speedup vs baseline: 1.1379x; 1.0571x over previous
#include <cuda_runtime.h>

// LiveniumJoint closed form: h stays in span{h0, a0n, a1n, a2n}.
// R15 = R14 resubmitted (infra failure, never ran).
// R9 memory shape (reg anchors + in-kernel per-warp prep, j-outer 24-LDG
// burst, L2 prefetch of next batch with the burst, output from h regs,
// 1024-block grid) + scale-invariant direction-space chain:
//   v' = (beta*v + alpha*t)/sqrt(d),  d = 1 + a^2(t^2 - c^2)
// alignments V tracked directly; clip is a scalar min on the norm m;
// one rsqrt + one rcp + three ex2 per iteration.

#define DD 768
#define VV 192            // float4 per row
#define KPL 6             // float4 per lane (192/32)
#define RB 4              // rows per warp-batch
#define FULLMASK 0xffffffffu

__device__ __forceinline__ float rcpa(float x) {
    float y; asm("rcp.approx.ftz.f32 %0,%1;" : "=f"(y) : "f"(x)); return y;
}
__device__ __forceinline__ float rsqa(float x) {
    float y; asm("rsqrt.approx.ftz.f32 %0,%1;" : "=f"(y) : "f"(x)); return y;
}
__device__ __forceinline__ float ex2a(float x) {
    float y; asm("ex2.approx.ftz.f32 %0,%1;" : "=f"(y) : "f"(x)); return y;
}
__device__ __forceinline__ void pfL2(const void* p) {
    asm volatile("prefetch.global.L2 [%0];" :: "l"(p));
}

__global__ void liv_fused(const float* __restrict__ h0,
                          const float* __restrict__ anchors,
                          float* __restrict__ out_h,
                          float* __restrict__ out_al,
                          int B) {
    const int tid = threadIdx.x, lane = tid & 31;

    // ---- per-warp anchor prep, all in registers (anchors L2-hot) ----
    float4 A0[KPL], A1[KPL], A2[KPL];
    {
        const float4* av = (const float4*)anchors;
        #pragma unroll
        for (int k = 0; k < KPL; k++) {
            A0[k] = __ldg(av + k * 32 + lane);
            A1[k] = __ldg(av + VV + k * 32 + lane);
            A2[k] = __ldg(av + 2 * VV + k * 32 + lane);
        }
    }
    float n0 = 0.f, n1 = 0.f, n2 = 0.f, d01 = 0.f, d02 = 0.f, d12 = 0.f;
    #pragma unroll
    for (int k = 0; k < KPL; k++) {
        n0 = fmaf(A0[k].x, A0[k].x, n0); n0 = fmaf(A0[k].y, A0[k].y, n0);
        n0 = fmaf(A0[k].z, A0[k].z, n0); n0 = fmaf(A0[k].w, A0[k].w, n0);
        n1 = fmaf(A1[k].x, A1[k].x, n1); n1 = fmaf(A1[k].y, A1[k].y, n1);
        n1 = fmaf(A1[k].z, A1[k].z, n1); n1 = fmaf(A1[k].w, A1[k].w, n1);
        n2 = fmaf(A2[k].x, A2[k].x, n2); n2 = fmaf(A2[k].y, A2[k].y, n2);
        n2 = fmaf(A2[k].z, A2[k].z, n2); n2 = fmaf(A2[k].w, A2[k].w, n2);
        d01 = fmaf(A0[k].x, A1[k].x, d01); d01 = fmaf(A0[k].y, A1[k].y, d01);
        d01 = fmaf(A0[k].z, A1[k].z, d01); d01 = fmaf(A0[k].w, A1[k].w, d01);
        d02 = fmaf(A0[k].x, A2[k].x, d02); d02 = fmaf(A0[k].y, A2[k].y, d02);
        d02 = fmaf(A0[k].z, A2[k].z, d02); d02 = fmaf(A0[k].w, A2[k].w, d02);
        d12 = fmaf(A1[k].x, A2[k].x, d12); d12 = fmaf(A1[k].y, A2[k].y, d12);
        d12 = fmaf(A1[k].z, A2[k].z, d12); d12 = fmaf(A1[k].w, A2[k].w, d12);
    }
    #pragma unroll
    for (int o = 16; o; o >>= 1) {
        n0  += __shfl_xor_sync(FULLMASK, n0,  o);
        n1  += __shfl_xor_sync(FULLMASK, n1,  o);
        n2  += __shfl_xor_sync(FULLMASK, n2,  o);
        d01 += __shfl_xor_sync(FULLMASK, d01, o);
        d02 += __shfl_xor_sync(FULLMASK, d02, o);
        d12 += __shfl_xor_sync(FULLMASK, d12, o);
    }
    const float i0 = 1.f / fmaxf(sqrtf(n0), 1e-12f);
    const float i1 = 1.f / fmaxf(sqrtf(n1), 1e-12f);
    const float i2 = 1.f / fmaxf(sqrtf(n2), 1e-12f);
    #pragma unroll
    for (int k = 0; k < KPL; k++) {
        A0[k].x *= i0; A0[k].y *= i0; A0[k].z *= i0; A0[k].w *= i0;
        A1[k].x *= i1; A1[k].y *= i1; A1[k].z *= i1; A1[k].w *= i1;
        A2[k].x *= i2; A2[k].y *= i2; A2[k].z *= i2; A2[k].w *= i2;
    }
    const float G00 = n0 * i0 * i0, G11 = n1 * i1 * i1, G22 = n2 * i2 * i2;
    const float G01 = d01 * i0 * i1, G02 = d02 * i0 * i2, G12 = d12 * i1 * i2;

    const int gw = (blockIdx.x * blockDim.x + tid) >> 5;
    const int nwarps = (gridDim.x * blockDim.x) >> 5;
    const int nbatch = (B + RB - 1) / RB;
    const float4* hp = (const float4*)h0;

    for (int b = gw; b < nbatch; b += nwarps) {
        const int base = b * RB;

        // ---- burst: 24 LDG.128 in flight ----
        float4 h[RB][KPL];
        #pragma unroll
        for (int j = 0; j < RB; j++) {
            int row = base + j; if (row >= B) row = B - 1;
            const float4* rp = hp + (size_t)row * VV;
            #pragma unroll
            for (int k = 0; k < KPL; k++) h[j][k] = __ldg(rp + k * 32 + lane);
        }

        // ---- L2-prefetch next batch (96 lines, 3 warp instructions) ----
        {
            const int nb = b + nwarps;
            if (nb < nbatch) {
                const size_t nbase = (size_t)nb * RB;
                #pragma unroll
                for (int t = 0; t < 3; t++) {
                    int f = t * 32 + lane;            // 0..95
                    int r = f / 24, lc = f - r * 24;  // row, 128B line
                    const char* a = (const char*)(hp + (nbase + r) * VV) + lc * 128;
                    pfL2(a);
                }
            }
        }

        // ---- per-row dots + reduce; park scalars in lane j ----
        float myN = 0.f, myT0 = 0.f, myT1 = 0.f, myT2 = 0.f;
        #pragma unroll
        for (int j = 0; j < RB; j++) {
            float N0 = 0.f, T0 = 0.f, T1 = 0.f, T2 = 0.f;
            #pragma unroll
            for (int k = 0; k < KPL; k++) {
                const float4 v = h[j][k];
                N0 = fmaf(v.x, v.x, N0);
                N0 = fmaf(v.y, v.y, N0);
                N0 = fmaf(v.z, v.z, N0);
                N0 = fmaf(v.w, v.w, N0);
                T0 = fmaf(v.x, A0[k].x, T0);
                T0 = fmaf(v.y, A0[k].y, T0);
                T0 = fmaf(v.z, A0[k].z, T0);
                T0 = fmaf(v.w, A0[k].w, T0);
                T1 = fmaf(v.x, A1[k].x, T1);
                T1 = fmaf(v.y, A1[k].y, T1);
                T1 = fmaf(v.z, A1[k].z, T1);
                T1 = fmaf(v.w, A1[k].w, T1);
                T2 = fmaf(v.x, A2[k].x, T2);
                T2 = fmaf(v.y, A2[k].y, T2);
                T2 = fmaf(v.z, A2[k].z, T2);
                T2 = fmaf(v.w, A2[k].w, T2);
            }
            #pragma unroll
            for (int o = 16; o; o >>= 1) {
                N0 += __shfl_xor_sync(FULLMASK, N0, o);
                T0 += __shfl_xor_sync(FULLMASK, T0, o);
                T1 += __shfl_xor_sync(FULLMASK, T1, o);
                T2 += __shfl_xor_sync(FULLMASK, T2, o);
            }
            if (lane == j) { myN = N0; myT0 = T0; myT1 = T1; myT2 = T2; }
        }

        // ---- scale-invariant direction chain: lane j = row base+j ----
        // v = h/|h|; V_i = <v, a_i>; h = m * (P*h0 + Q.a)
        const float invn = rsqa(fmaxf(myN, 1e-24f));
        float m  = myN * invn;                     // |h0|
        float V0 = myT0 * invn, V1 = myT1 * invn, V2 = myT2 * invn;
        float P  = invn, Q0 = 0.f, Q1 = 0.f, Q2 = 0.f;
        const float KK = 28.853900817779268f;      // 20 * log2(e)
        #pragma unroll
        for (int s = 0; s < 6; s++) {
            // softmax(20 * V)
            float e0 = ex2a(KK * V0);
            float e1 = ex2a(KK * V1);
            float e2 = ex2a(KK * V2);
            float invW = rcpa(e0 + e1 + e2);
            float w0 = e0 * invW, w1 = e1 * invW, w2 = e2 * invW;

            // g = G w ; c = w.V ; t2 = w.g
            float g0 = fmaf(w0, G00, fmaf(w1, G01, w2 * G02));
            float g1 = fmaf(w0, G01, fmaf(w1, G11, w2 * G12));
            float g2 = fmaf(w0, G02, fmaf(w1, G12, w2 * G22));
            float c  = fmaf(w0, V0, fmaf(w1, V1, w2 * V2));
            float t2 = fmaf(w0, g0, fmaf(w1, g1, w2 * g2));

            float d    = fmaf(0.0025f, t2 - c * c, 1.f);  // |v'|^2 pre-norm
            float r    = rsqa(d);                          // 1/sqrt(d)
            float beta = fmaf(-0.05f, c, 1.f);
            float br   = beta * r;

            V0 = fmaf(br, V0, 0.05f * r * g0);
            V1 = fmaf(br, V1, 0.05f * r * g1);
            V2 = fmaf(br, V2, 0.05f * r * g2);
            P  = P * br;
            Q0 = fmaf(br, Q0, 0.05f * r * w0);
            Q1 = fmaf(br, Q1, 0.05f * r * w1);
            Q2 = fmaf(br, Q2, 0.05f * r * w2);

            // norm: m' = m * sqrt(d) = m * d * r, clipped at 10
            m = fminf(m * d * r, 10.f);
        }
        // final alignments = V (already normalized); h = m*(P h0 + Q.a)
        float p  = m * P;
        float q0 = m * Q0, q1 = m * Q1, q2 = m * Q2;

        // ---- outputs: broadcast (p,q) from lane j, h from regs ----
        #pragma unroll
        for (int j = 0; j < RB; j++) {
            const int row = base + j;
            const float pj  = __shfl_sync(FULLMASK, p,  j);
            const float q0j = __shfl_sync(FULLMASK, q0, j);
            const float q1j = __shfl_sync(FULLMASK, q1, j);
            const float q2j = __shfl_sync(FULLMASK, q2, j);
            if (row < B) {
                float4* op = (float4*)out_h + (size_t)row * VV;
                #pragma unroll
                for (int k = 0; k < KPL; k++) {
                    float4 o;
                    o.x = fmaf(pj, h[j][k].x, fmaf(q0j, A0[k].x, fmaf(q1j, A1[k].x, q2j * A2[k].x)));
                    o.y = fmaf(pj, h[j][k].y, fmaf(q0j, A0[k].y, fmaf(q1j, A1[k].y, q2j * A2[k].y)));
                    o.z = fmaf(pj, h[j][k].z, fmaf(q0j, A0[k].z, fmaf(q1j, A1[k].z, q2j * A2[k].z)));
                    o.w = fmaf(pj, h[j][k].w, fmaf(q0j, A0[k].w, fmaf(q1j, A1[k].w, q2j * A2[k].w)));
                    op[k * 32 + lane] = o;
                }
            }
        }
        if (lane < RB && base + lane < B) {
            float* ap = out_al + (size_t)(base + lane) * 3;
            ap[0] = V0; ap[1] = V1; ap[2] = V2;
        }
    }
}

// ---------------------------------------------------------------------------
extern "C" void kernel_launch(void* const* d_in, const int* in_sizes, int n_in,
                              void* d_out, int out_size) {
    const float* h0 = (const float*)d_in[0];       // [B, 768]
    const float* anchors = (const float*)d_in[1];  // [3, 768]
    const int B = in_sizes[0] / DD;

    float* out_h = (float*)d_out;                    // [B, 768]
    float* out_al = (float*)d_out + (size_t)B * DD;  // [B, 3]

    const int threads = 128;              // 4 warps/block
    int nbatch = (B + RB - 1) / RB;       // 16384 batches of 4 rows
    int blocks = 1024;                    // R9's proven grid
    int total_warps = blocks * (threads / 32);
    if (total_warps > nbatch) blocks = (nbatch + 3) / 4;
    liv_fused<<<blocks, threads>>>(h0, anchors, out_h, out_al, B);
}

// round 16
// speedup vs baseline: 1.1714x; 1.0294x over previous
#include <cuda_runtime.h>

// LiveniumJoint closed form: h stays in span{h0, a0n, a1n, a2n}.
// R16 = R15 (R9 memory shape + scale-invariant direction chain) with dots
// and outputs converted to packed f32x2 FMA (fma.rn.f32x2 / mul.rn.f32x2,
// sm_100+): two fp32 FMAs per instruction, ~380 fewer instr per batch.

#define DD 768
#define VV 192            // float4 per row
#define KPL 6             // float4 per lane (192/32)
#define RB 4              // rows per warp-batch
#define FULLMASK 0xffffffffu

typedef unsigned long long u64;

__device__ __forceinline__ float rcpa(float x) {
    float y; asm("rcp.approx.ftz.f32 %0,%1;" : "=f"(y) : "f"(x)); return y;
}
__device__ __forceinline__ float rsqa(float x) {
    float y; asm("rsqrt.approx.ftz.f32 %0,%1;" : "=f"(y) : "f"(x)); return y;
}
__device__ __forceinline__ float ex2a(float x) {
    float y; asm("ex2.approx.ftz.f32 %0,%1;" : "=f"(y) : "f"(x)); return y;
}
__device__ __forceinline__ void pfL2(const void* p) {
    asm volatile("prefetch.global.L2 [%0];" :: "l"(p));
}
// ---- packed f32x2 ops (sm_100+) ----
__device__ __forceinline__ u64 fma2(u64 a, u64 b, u64 c) {
    u64 d; asm("fma.rn.f32x2 %0, %1, %2, %3;" : "=l"(d) : "l"(a), "l"(b), "l"(c));
    return d;
}
__device__ __forceinline__ u64 mul2(u64 a, u64 b) {
    u64 d; asm("mul.rn.f32x2 %0, %1, %2;" : "=l"(d) : "l"(a), "l"(b));
    return d;
}
__device__ __forceinline__ u64 pack2(float x) {
    u64 d; asm("mov.b64 %0, {%1, %1};" : "=l"(d) : "f"(x));
    return d;
}
__device__ __forceinline__ float hsum2(u64 v) {
    float lo, hi; asm("mov.b64 {%0, %1}, %2;" : "=f"(lo), "=f"(hi) : "l"(v));
    return lo + hi;
}
union F4U2 { float4 f; ulonglong2 u; };
__device__ __forceinline__ ulonglong2 asU2(float4 v) { F4U2 c; c.f = v; return c.u; }
__device__ __forceinline__ float4 asF4(ulonglong2 u) { F4U2 c; c.u = u; return c.f; }

__global__ void liv_fused(const float* __restrict__ h0,
                          const float* __restrict__ anchors,
                          float* __restrict__ out_h,
                          float* __restrict__ out_al,
                          int B) {
    const int tid = threadIdx.x, lane = tid & 31;

    // ---- per-warp anchor prep, all in registers (anchors L2-hot) ----
    float4 A0[KPL], A1[KPL], A2[KPL];
    {
        const float4* av = (const float4*)anchors;
        #pragma unroll
        for (int k = 0; k < KPL; k++) {
            A0[k] = __ldg(av + k * 32 + lane);
            A1[k] = __ldg(av + VV + k * 32 + lane);
            A2[k] = __ldg(av + 2 * VV + k * 32 + lane);
        }
    }
    float n0 = 0.f, n1 = 0.f, n2 = 0.f, d01 = 0.f, d02 = 0.f, d12 = 0.f;
    #pragma unroll
    for (int k = 0; k < KPL; k++) {
        n0 = fmaf(A0[k].x, A0[k].x, n0); n0 = fmaf(A0[k].y, A0[k].y, n0);
        n0 = fmaf(A0[k].z, A0[k].z, n0); n0 = fmaf(A0[k].w, A0[k].w, n0);
        n1 = fmaf(A1[k].x, A1[k].x, n1); n1 = fmaf(A1[k].y, A1[k].y, n1);
        n1 = fmaf(A1[k].z, A1[k].z, n1); n1 = fmaf(A1[k].w, A1[k].w, n1);
        n2 = fmaf(A2[k].x, A2[k].x, n2); n2 = fmaf(A2[k].y, A2[k].y, n2);
        n2 = fmaf(A2[k].z, A2[k].z, n2); n2 = fmaf(A2[k].w, A2[k].w, n2);
        d01 = fmaf(A0[k].x, A1[k].x, d01); d01 = fmaf(A0[k].y, A1[k].y, d01);
        d01 = fmaf(A0[k].z, A1[k].z, d01); d01 = fmaf(A0[k].w, A1[k].w, d01);
        d02 = fmaf(A0[k].x, A2[k].x, d02); d02 = fmaf(A0[k].y, A2[k].y, d02);
        d02 = fmaf(A0[k].z, A2[k].z, d02); d02 = fmaf(A0[k].w, A2[k].w, d02);
        d12 = fmaf(A1[k].x, A2[k].x, d12); d12 = fmaf(A1[k].y, A2[k].y, d12);
        d12 = fmaf(A1[k].z, A2[k].z, d12); d12 = fmaf(A1[k].w, A2[k].w, d12);
    }
    #pragma unroll
    for (int o = 16; o; o >>= 1) {
        n0  += __shfl_xor_sync(FULLMASK, n0,  o);
        n1  += __shfl_xor_sync(FULLMASK, n1,  o);
        n2  += __shfl_xor_sync(FULLMASK, n2,  o);
        d01 += __shfl_xor_sync(FULLMASK, d01, o);
        d02 += __shfl_xor_sync(FULLMASK, d02, o);
        d12 += __shfl_xor_sync(FULLMASK, d12, o);
    }
    const float i0 = 1.f / fmaxf(sqrtf(n0), 1e-12f);
    const float i1 = 1.f / fmaxf(sqrtf(n1), 1e-12f);
    const float i2 = 1.f / fmaxf(sqrtf(n2), 1e-12f);
    #pragma unroll
    for (int k = 0; k < KPL; k++) {
        A0[k].x *= i0; A0[k].y *= i0; A0[k].z *= i0; A0[k].w *= i0;
        A1[k].x *= i1; A1[k].y *= i1; A1[k].z *= i1; A1[k].w *= i1;
        A2[k].x *= i2; A2[k].y *= i2; A2[k].z *= i2; A2[k].w *= i2;
    }
    const float G00 = n0 * i0 * i0, G11 = n1 * i1 * i1, G22 = n2 * i2 * i2;
    const float G01 = d01 * i0 * i1, G02 = d02 * i0 * i2, G12 = d12 * i1 * i2;

    const int gw = (blockIdx.x * blockDim.x + tid) >> 5;
    const int nwarps = (gridDim.x * blockDim.x) >> 5;
    const int nbatch = (B + RB - 1) / RB;
    const float4* hp = (const float4*)h0;

    for (int b = gw; b < nbatch; b += nwarps) {
        const int base = b * RB;

        // ---- burst: 24 LDG.128 in flight ----
        float4 h[RB][KPL];
        #pragma unroll
        for (int j = 0; j < RB; j++) {
            int row = base + j; if (row >= B) row = B - 1;
            const float4* rp = hp + (size_t)row * VV;
            #pragma unroll
            for (int k = 0; k < KPL; k++) h[j][k] = __ldg(rp + k * 32 + lane);
        }

        // ---- L2-prefetch next batch (96 lines, 3 warp instructions) ----
        {
            const int nb = b + nwarps;
            if (nb < nbatch) {
                const size_t nbase = (size_t)nb * RB;
                #pragma unroll
                for (int t = 0; t < 3; t++) {
                    int f = t * 32 + lane;            // 0..95
                    int r = f / 24, lc = f - r * 24;  // row, 128B line
                    const char* a = (const char*)(hp + (nbase + r) * VV) + lc * 128;
                    pfL2(a);
                }
            }
        }

        // ---- per-row dots (packed f32x2) + reduce; park scalars in lane j ----
        float myN = 0.f, myT0 = 0.f, myT1 = 0.f, myT2 = 0.f;
        #pragma unroll
        for (int j = 0; j < RB; j++) {
            u64 aN = 0ull, aT0 = 0ull, aT1 = 0ull, aT2 = 0ull;
            #pragma unroll
            for (int k = 0; k < KPL; k++) {
                const ulonglong2 hv = asU2(h[j][k]);
                const ulonglong2 a0 = asU2(A0[k]);
                const ulonglong2 a1 = asU2(A1[k]);
                const ulonglong2 a2 = asU2(A2[k]);
                aN  = fma2(hv.x, hv.x, aN);
                aN  = fma2(hv.y, hv.y, aN);
                aT0 = fma2(hv.x, a0.x, aT0);
                aT0 = fma2(hv.y, a0.y, aT0);
                aT1 = fma2(hv.x, a1.x, aT1);
                aT1 = fma2(hv.y, a1.y, aT1);
                aT2 = fma2(hv.x, a2.x, aT2);
                aT2 = fma2(hv.y, a2.y, aT2);
            }
            float N0 = hsum2(aN);
            float T0 = hsum2(aT0);
            float T1 = hsum2(aT1);
            float T2 = hsum2(aT2);
            #pragma unroll
            for (int o = 16; o; o >>= 1) {
                N0 += __shfl_xor_sync(FULLMASK, N0, o);
                T0 += __shfl_xor_sync(FULLMASK, T0, o);
                T1 += __shfl_xor_sync(FULLMASK, T1, o);
                T2 += __shfl_xor_sync(FULLMASK, T2, o);
            }
            if (lane == j) { myN = N0; myT0 = T0; myT1 = T1; myT2 = T2; }
        }

        // ---- scale-invariant direction chain: lane j = row base+j ----
        const float invn = rsqa(fmaxf(myN, 1e-24f));
        float m  = myN * invn;                     // |h0|
        float V0 = myT0 * invn, V1 = myT1 * invn, V2 = myT2 * invn;
        float P  = invn, Q0 = 0.f, Q1 = 0.f, Q2 = 0.f;
        const float KK = 28.853900817779268f;      // 20 * log2(e)
        #pragma unroll
        for (int s = 0; s < 6; s++) {
            float e0 = ex2a(KK * V0);
            float e1 = ex2a(KK * V1);
            float e2 = ex2a(KK * V2);
            float invW = rcpa(e0 + e1 + e2);
            float w0 = e0 * invW, w1 = e1 * invW, w2 = e2 * invW;

            float g0 = fmaf(w0, G00, fmaf(w1, G01, w2 * G02));
            float g1 = fmaf(w0, G01, fmaf(w1, G11, w2 * G12));
            float g2 = fmaf(w0, G02, fmaf(w1, G12, w2 * G22));
            float c  = fmaf(w0, V0, fmaf(w1, V1, w2 * V2));
            float t2 = fmaf(w0, g0, fmaf(w1, g1, w2 * g2));

            float d    = fmaf(0.0025f, t2 - c * c, 1.f);  // |v'|^2 pre-norm
            float r    = rsqa(d);                          // 1/sqrt(d)
            float beta = fmaf(-0.05f, c, 1.f);
            float br   = beta * r;

            V0 = fmaf(br, V0, 0.05f * r * g0);
            V1 = fmaf(br, V1, 0.05f * r * g1);
            V2 = fmaf(br, V2, 0.05f * r * g2);
            P  = P * br;
            Q0 = fmaf(br, Q0, 0.05f * r * w0);
            Q1 = fmaf(br, Q1, 0.05f * r * w1);
            Q2 = fmaf(br, Q2, 0.05f * r * w2);

            m = fminf(m * d * r, 10.f);                    // clip = scalar min
        }
        float p  = m * P;
        float q0 = m * Q0, q1 = m * Q1, q2 = m * Q2;

        // ---- outputs: packed f32x2, broadcast (p,q) from lane j ----
        #pragma unroll
        for (int j = 0; j < RB; j++) {
            const int row = base + j;
            const u64 pj2  = pack2(__shfl_sync(FULLMASK, p,  j));
            const u64 q0j2 = pack2(__shfl_sync(FULLMASK, q0, j));
            const u64 q1j2 = pack2(__shfl_sync(FULLMASK, q1, j));
            const u64 q2j2 = pack2(__shfl_sync(FULLMASK, q2, j));
            if (row < B) {
                float4* op = (float4*)out_h + (size_t)row * VV;
                #pragma unroll
                for (int k = 0; k < KPL; k++) {
                    const ulonglong2 hv = asU2(h[j][k]);
                    const ulonglong2 a0 = asU2(A0[k]);
                    const ulonglong2 a1 = asU2(A1[k]);
                    const ulonglong2 a2 = asU2(A2[k]);
                    ulonglong2 o;
                    o.x = fma2(pj2, hv.x, fma2(q0j2, a0.x, fma2(q1j2, a1.x, mul2(q2j2, a2.x))));
                    o.y = fma2(pj2, hv.y, fma2(q0j2, a0.y, fma2(q1j2, a1.y, mul2(q2j2, a2.y))));
                    op[k * 32 + lane] = asF4(o);
                }
            }
        }
        if (lane < RB && base + lane < B) {
            float* ap = out_al + (size_t)(base + lane) * 3;
            ap[0] = V0; ap[1] = V1; ap[2] = V2;
        }
    }
}

// ---------------------------------------------------------------------------
extern "C" void kernel_launch(void* const* d_in, const int* in_sizes, int n_in,
                              void* d_out, int out_size) {
    const float* h0 = (const float*)d_in[0];       // [B, 768]
    const float* anchors = (const float*)d_in[1];  // [3, 768]
    const int B = in_sizes[0] / DD;

    float* out_h = (float*)d_out;                    // [B, 768]
    float* out_al = (float*)d_out + (size_t)B * DD;  // [B, 3]

    const int threads = 128;              // 4 warps/block
    int nbatch = (B + RB - 1) / RB;       // 16384 batches of 4 rows
    int blocks = 1024;                    // proven grid
    int total_warps = blocks * (threads / 32);
    if (total_warps > nbatch) blocks = (nbatch + 3) / 4;
    liv_fused<<<blocks, threads>>>(h0, anchors, out_h, out_al, B);
}